// round 2
// baseline (speedup 1.0000x reference)
#include <cuda_runtime.h>

#define NN 100000
#define EE 1600000
#define CAP 64

// ---- scratch (static __device__ allocations only, per harness rules) ----
__device__ int   g_deg[NN];
__device__ int   g_adj[NN * CAP];     // per-dst src lists (counting bucket sort)
__device__ float g_U[NN * 64];        // per-node precomputed  x@(Wa_top-Wa_bot)+ba
__device__ float g_V[NN * 64];        // per-node precomputed  x@Wa_bot
__device__ float g_H[NN * 64];        // layer-1 output (post relu/fill)

// ---------------------------------------------------------------- zero degs
__global__ void k_zero() {
    int i = blockIdx.x * blockDim.x + threadIdx.x;
    if (i < NN) g_deg[i] = 0;
}

// ------------------------------------------------- bucket edges by dst node
__global__ void k_scatter(const int* __restrict__ ei) {
    int e = blockIdx.x * blockDim.x + threadIdx.x;
    if (e >= EE) return;
    int s = ei[e];          // src row
    int d = ei[EE + e];     // dst row
    int p = atomicAdd(&g_deg[d], 1);
    if (p < CAP) g_adj[d * CAP + p] = s;
}

// ------------------------------------- layer-1 per-node U,V from x (K = 7)
__global__ void __launch_bounds__(128) k_uv1(const float* __restrict__ x,
                                             const float* __restrict__ W1a,
                                             const float* __restrict__ b1a) {
    __shared__ float sW[14 * 64];
    __shared__ float sb[64];
    for (int t = threadIdx.x; t < 14 * 64; t += blockDim.x) sW[t] = W1a[t];
    for (int t = threadIdx.x; t < 64; t += blockDim.x) sb[t] = b1a[t];
    __syncthreads();

    int warp = threadIdx.x >> 5, lane = threadIdx.x & 31;
    int i = blockIdx.x * 4 + warp;
    if (i >= NN) return;
    int c0 = 2 * lane, c1 = c0 + 1;

    float xv[7];
#pragma unroll
    for (int k = 0; k < 7; k++) xv[k] = x[i * 7 + k];   // broadcast in warp

    float u0 = sb[c0], u1 = sb[c1], v0 = 0.f, v1 = 0.f;
#pragma unroll
    for (int k = 0; k < 7; k++) {
        float wt0 = sW[k * 64 + c0], wt1 = sW[k * 64 + c1];
        float wb0 = sW[(7 + k) * 64 + c0], wb1 = sW[(7 + k) * 64 + c1];
        u0 = fmaf(xv[k], wt0 - wb0, u0);
        u1 = fmaf(xv[k], wt1 - wb1, u1);
        v0 = fmaf(xv[k], wb0, v0);
        v1 = fmaf(xv[k], wb1, v1);
    }
    *(float2*)&g_U[i * 64 + c0] = make_float2(u0, u1);
    *(float2*)&g_V[i * 64 + c0] = make_float2(v0, v1);
}

// ------------------------------------ layer-2 per-node U,V from H (K = 64)
__global__ void __launch_bounds__(128) k_uv2(const float* __restrict__ W2a,
                                             const float* __restrict__ b2a) {
    __shared__ float sWt[64 * 64];
    __shared__ float sWb[64 * 64];
    __shared__ float sb[64];
    __shared__ float sh[4][64];
    for (int t = threadIdx.x; t < 4096; t += blockDim.x) {
        sWt[t] = W2a[t];
        sWb[t] = W2a[4096 + t];
    }
    for (int t = threadIdx.x; t < 64; t += blockDim.x) sb[t] = b2a[t];
    __syncthreads();

    int warp = threadIdx.x >> 5, lane = threadIdx.x & 31;
    int c0 = 2 * lane, c1 = c0 + 1;
    float* shw = sh[warp];
    int nwarps = gridDim.x * 4;

    for (int i = blockIdx.x * 4 + warp; i < NN; i += nwarps) {
        float2 h2 = *(const float2*)&g_H[i * 64 + c0];
        shw[c0] = h2.x; shw[c1] = h2.y;
        __syncwarp();
        float u0 = sb[c0], u1 = sb[c1], v0 = 0.f, v1 = 0.f;
        const float4* h4p = (const float4*)shw;
#pragma unroll
        for (int kk = 0; kk < 16; kk++) {
            float4 h4 = h4p[kk];
#pragma unroll
            for (int q = 0; q < 4; q++) {
                int k = 4 * kk + q;
                float hk = (q == 0) ? h4.x : (q == 1) ? h4.y : (q == 2) ? h4.z : h4.w;
                float2 wt = *(const float2*)&sWt[k * 64 + c0];
                float2 wb = *(const float2*)&sWb[k * 64 + c0];
                u0 = fmaf(hk, wt.x - wb.x, u0);
                u1 = fmaf(hk, wt.y - wb.y, u1);
                v0 = fmaf(hk, wb.x, v0);
                v1 = fmaf(hk, wb.y, v1);
            }
        }
        __syncwarp();
        *(float2*)&g_U[i * 64 + c0] = make_float2(u0, u1);
        *(float2*)&g_V[i * 64 + c0] = make_float2(v0, v1);
    }
}

// -------- hot kernel: per-node max-aggregate of relu(U[i]+V[j]) @ Wb + bb
// warp per node, 2 output channels per thread, Wb columns in registers,
// t broadcast through smem. acc starts at 0 => fused relu + empty-node fill.
template <bool FINAL>
__global__ void __launch_bounds__(128) k_layer(const float* __restrict__ Wb,
                                               const float* __restrict__ bb,
                                               const float* __restrict__ Wl,
                                               const float* __restrict__ bl,
                                               float* __restrict__ out) {
    __shared__ float sW[64 * 64];
    __shared__ float st[4][64];
    for (int t = threadIdx.x; t < 4096; t += blockDim.x) sW[t] = Wb[t];
    __syncthreads();

    int warp = threadIdx.x >> 5, lane = threadIdx.x & 31;
    int c0 = 2 * lane, c1 = c0 + 1;

    float w0[64], w1[64];
#pragma unroll
    for (int k = 0; k < 64; k++) {
        w0[k] = sW[k * 64 + c0];
        w1[k] = sW[k * 64 + c1];
    }
    float bb0 = bb[c0], bb1 = bb[c1];
    float wl0 = 0.f, wl1 = 0.f, blv = 0.f;
    if (FINAL) { wl0 = Wl[c0]; wl1 = Wl[c1]; blv = bl[0]; }

    float* stw = st[warp];
    int nwarps = gridDim.x * 4;

    for (int i = blockIdx.x * 4 + warp; i < NN; i += nwarps) {
        int dg = g_deg[i];
        if (dg > CAP) dg = CAP;
        const int* adj = &g_adj[i * CAP];
        float2 uu = *(const float2*)&g_U[i * 64 + c0];
        float a0 = 0.f, a1 = 0.f;

        float2 vp = make_float2(0.f, 0.f);
        if (dg > 0) {
            int j0 = adj[0];
            vp = *(const float2*)&g_V[j0 * 64 + c0];
        }
        for (int e = 0; e < dg; e++) {
            float2 vv = vp;
            if (e + 1 < dg) {
                int jn = adj[e + 1];
                vp = *(const float2*)&g_V[jn * 64 + c0];   // prefetch next edge
            }
            float t0 = fmaxf(uu.x + vv.x, 0.f);
            float t1 = fmaxf(uu.y + vv.y, 0.f);
            stw[c0] = t0; stw[c1] = t1;
            __syncwarp();
            float z0 = 0.f, z1 = 0.f, z2 = 0.f, z3 = 0.f;
            float y0 = 0.f, y1 = 0.f, y2 = 0.f, y3 = 0.f;
            const float4* t4p = (const float4*)stw;
#pragma unroll
            for (int kk = 0; kk < 16; kk++) {
                float4 t4 = t4p[kk];
                z0 = fmaf(w0[4 * kk + 0], t4.x, z0);
                z1 = fmaf(w0[4 * kk + 1], t4.y, z1);
                z2 = fmaf(w0[4 * kk + 2], t4.z, z2);
                z3 = fmaf(w0[4 * kk + 3], t4.w, z3);
                y0 = fmaf(w1[4 * kk + 0], t4.x, y0);
                y1 = fmaf(w1[4 * kk + 1], t4.y, y1);
                y2 = fmaf(w1[4 * kk + 2], t4.z, y2);
                y3 = fmaf(w1[4 * kk + 3], t4.w, y3);
            }
            __syncwarp();
            a0 = fmaxf(a0, (z0 + z1) + (z2 + z3) + bb0);
            a1 = fmaxf(a1, (y0 + y1) + (y2 + y3) + bb1);
        }

        if (FINAL) {
            float p = a0 * wl0 + a1 * wl1;
#pragma unroll
            for (int off = 16; off; off >>= 1)
                p += __shfl_xor_sync(0xffffffffu, p, off);
            if (lane == 0) out[i] = p + blv;
        } else {
            *(float2*)&g_H[i * 64 + c0] = make_float2(a0, a1);
        }
    }
}

extern "C" void kernel_launch(void* const* d_in, const int* in_sizes, int n_in,
                              void* d_out, int out_size) {
    const float* x   = (const float*)d_in[0];
    const int*   ei  = (const int*)d_in[1];
    const float* W1a = (const float*)d_in[2];
    const float* b1a = (const float*)d_in[3];
    const float* W1b = (const float*)d_in[4];
    const float* b1b = (const float*)d_in[5];
    const float* W2a = (const float*)d_in[6];
    const float* b2a = (const float*)d_in[7];
    const float* W2b = (const float*)d_in[8];
    const float* b2b = (const float*)d_in[9];
    const float* Wl  = (const float*)d_in[10];
    const float* bl  = (const float*)d_in[11];
    float* out = (float*)d_out;

    k_zero<<<(NN + 255) / 256, 256>>>();
    k_scatter<<<(EE + 255) / 256, 256>>>(ei);
    k_uv1<<<(NN + 3) / 4, 128>>>(x, W1a, b1a);
    k_layer<false><<<1184, 128>>>(W1b, b1b, nullptr, nullptr, nullptr);
    k_uv2<<<888, 128>>>(W2a, b2a);
    k_layer<true><<<1184, 128>>>(W2b, b2b, Wl, bl, out);
}